// round 1
// baseline (speedup 1.0000x reference)
#include <cuda_runtime.h>
#include <math.h>
#include <float.h>

#define NQ   1024
#define MP   100000
#define DIM  256
#define KTOP 7
#define QB   64
#define PB   64
#define DK   8
#define SCH  32
#define CHUNK 3200   // 50 tiles of 64; 32*3200 = 102400 >= 100000

// ---------------- scratch (no allocations allowed) ----------------
__device__ float g_qn[NQ * DIM];      // normalized queries
__device__ float g_eq[NQ];            // exp(+lambda*qt)
__device__ float g_ieq[NQ];           // exp(-lambda*qt)
__device__ float g_pinv[MP];          // 1/max(||p||,eps)
__device__ float g_ep[MP];            // exp(+lambda*pt)
__device__ float g_iep[MP];           // exp(-lambda*pt)
__device__ float g_pv[NQ * SCH * KTOP];
__device__ int   g_pi[NQ * SCH * KTOP];
__device__ int   g_topi[NQ * KTOP];

__device__ __forceinline__ bool better(float s1, int i1, float s2, int i2) {
    // matches jax.lax.top_k ordering: higher score first; tie -> lower index
    return (s1 > s2) || (s1 == s2 && i1 < i2);
}

// ---------------- kernel 0: query prep ----------------
__global__ void prep_query_kernel(const float* __restrict__ qe,
                                  const float* __restrict__ qt,
                                  const float* __restrict__ lam) {
    int row  = blockIdx.x * 8 + (threadIdx.x >> 5);
    int lane = threadIdx.x & 31;
    if (row >= NQ) return;
    const float4* src = (const float4*)(qe + row * DIM + lane * 8);
    float4 a = src[0], b = src[1];
    float ss = a.x*a.x + a.y*a.y + a.z*a.z + a.w*a.w
             + b.x*b.x + b.y*b.y + b.z*b.z + b.w*b.w;
    #pragma unroll
    for (int o = 16; o > 0; o >>= 1) ss += __shfl_xor_sync(0xffffffff, ss, o);
    float inv = 1.0f / fmaxf(sqrtf(ss), 1e-8f);
    float4* dst = (float4*)(g_qn + row * DIM + lane * 8);
    a.x *= inv; a.y *= inv; a.z *= inv; a.w *= inv;
    b.x *= inv; b.y *= inv; b.z *= inv; b.w *= inv;
    dst[0] = a; dst[1] = b;
    if (lane == 0) {
        float l = lam[0];
        float t = qt[row];
        g_eq[row]  = expf(l * t);
        g_ieq[row] = expf(-l * t);
    }
}

// ---------------- kernel 1: pool prep ----------------
__global__ void prep_pool_kernel(const float* __restrict__ pe,
                                 const float* __restrict__ pt,
                                 const float* __restrict__ lam) {
    int row  = blockIdx.x * 8 + (threadIdx.x >> 5);
    int lane = threadIdx.x & 31;
    if (row >= MP) return;
    const float4* src = (const float4*)(pe + row * DIM + lane * 8);
    float4 a = src[0], b = src[1];
    float ss = a.x*a.x + a.y*a.y + a.z*a.z + a.w*a.w
             + b.x*b.x + b.y*b.y + b.z*b.z + b.w*b.w;
    #pragma unroll
    for (int o = 16; o > 0; o >>= 1) ss += __shfl_xor_sync(0xffffffff, ss, o);
    if (lane == 0) {
        g_pinv[row] = 1.0f / fmaxf(sqrtf(ss), 1e-8f);
        float l = lam[0];
        float t = pt[row];
        g_ep[row]  = expf(l * t);
        g_iep[row] = expf(-l * t);
    }
}

// ---------------- kernel 2: fused GEMM + streaming top-7 ----------------
__global__ __launch_bounds__(256, 2)
void main_topk_kernel(const float* __restrict__ pool) {
    const int tid  = threadIdx.x;
    const int tx   = tid & 15;         // pool direction
    const int ty   = tid >> 4;         // query direction
    const int qBase   = blockIdx.x * QB;
    const int chunkId = blockIdx.y;
    const int chunkEnd = min((chunkId + 1) * CHUNK, MP);

    __shared__ float qs[DK][QB];
    __shared__ float ps[DK][PB];
    __shared__ float seq[QB], sieq[QB];
    __shared__ float mbv[32][16 * KTOP];
    __shared__ int   mbi[32][16 * KTOP];

    if (tid < QB) {
        seq[tid]  = g_eq[qBase + tid];
        sieq[tid] = g_ieq[qBase + tid];
    }

    // per-thread top-7 state (arrays go to local mem; hot path uses registers)
    float lv[4][KTOP]; int li[4][KTOP];
    float lminv[4]; int lmini[4]; int lslot[4];
    #pragma unroll
    for (int i = 0; i < 4; i++) {
        #pragma unroll
        for (int t = 0; t < KTOP; t++) { lv[i][t] = -FLT_MAX; li[i][t] = 0x7fffffff; }
        lminv[i] = -FLT_MAX; lmini[i] = 0x7fffffff; lslot[i] = 0;
    }

    for (int pBase = chunkId * CHUNK; pBase < chunkEnd; pBase += PB) {
        float acc[4][4];
        #pragma unroll
        for (int i = 0; i < 4; i++)
            #pragma unroll
            for (int j = 0; j < 4; j++) acc[i][j] = 0.0f;

        for (int d0 = 0; d0 < DIM; d0 += DK) {
            __syncthreads();
            if (tid < 128) {
                int qi = tid >> 1;
                int kk = (tid & 1) * 4;
                float4 v = *(const float4*)&g_qn[(qBase + qi) * DIM + d0 + kk];
                qs[kk + 0][qi] = v.x; qs[kk + 1][qi] = v.y;
                qs[kk + 2][qi] = v.z; qs[kk + 3][qi] = v.w;
            } else {
                int t  = tid - 128;
                int pi = t >> 1;
                int kk = (t & 1) * 4;
                int p  = pBase + pi;
                float4 v = (p < MP) ? *(const float4*)&pool[(size_t)p * DIM + d0 + kk]
                                    : make_float4(0.f, 0.f, 0.f, 0.f);
                ps[kk + 0][pi] = v.x; ps[kk + 1][pi] = v.y;
                ps[kk + 2][pi] = v.z; ps[kk + 3][pi] = v.w;
            }
            __syncthreads();
            #pragma unroll
            for (int kk = 0; kk < DK; kk++) {
                float4 a = *(const float4*)&qs[kk][ty * 4];
                float4 b = *(const float4*)&ps[kk][tx * 4];
                acc[0][0] += a.x * b.x; acc[0][1] += a.x * b.y; acc[0][2] += a.x * b.z; acc[0][3] += a.x * b.w;
                acc[1][0] += a.y * b.x; acc[1][1] += a.y * b.y; acc[1][2] += a.y * b.z; acc[1][3] += a.y * b.w;
                acc[2][0] += a.z * b.x; acc[2][1] += a.z * b.y; acc[2][2] += a.z * b.z; acc[2][3] += a.z * b.w;
                acc[3][0] += a.w * b.x; acc[3][1] += a.w * b.y; acc[3][2] += a.w * b.z; acc[3][3] += a.w * b.w;
            }
        }

        // epilogue: scale, time-weight, top-7 update
        int p0 = pBase + tx * 4;
        float pvj[4], epj[4], iepj[4]; bool val[4];
        #pragma unroll
        for (int j = 0; j < 4; j++) {
            int p = p0 + j;
            val[j]  = (p < chunkEnd);
            pvj[j]  = val[j] ? g_pinv[p] : 0.f;
            epj[j]  = val[j] ? g_ep[p]   : 0.f;
            iepj[j] = val[j] ? g_iep[p]  : 0.f;
        }
        #pragma unroll
        for (int i = 0; i < 4; i++) {
            float eqv  = seq[ty * 4 + i];
            float ieqv = sieq[ty * 4 + i];
            #pragma unroll
            for (int j = 0; j < 4; j++) {
                if (!val[j]) continue;
                float tw = fminf(eqv * iepj[j], epj[j] * ieqv);
                float s  = acc[i][j] * pvj[j] * tw;
                int   p  = p0 + j;
                if (better(s, p, lminv[i], lmini[i])) {
                    lv[i][lslot[i]] = s; li[i][lslot[i]] = p;
                    float mv = lv[i][0]; int mi = li[i][0]; int ms = 0;
                    #pragma unroll
                    for (int t = 1; t < KTOP; t++) {
                        if (better(mv, mi, lv[i][t], li[i][t])) { mv = lv[i][t]; mi = li[i][t]; ms = t; }
                    }
                    lminv[i] = mv; lmini[i] = mi; lslot[i] = ms;
                }
            }
        }
    }

    // merge 16 per-thread lists per query -> sorted top-7 per (query, chunk)
    for (int pass = 0; pass < 2; pass++) {
        __syncthreads();
        if (ty >= pass * 8 && ty < pass * 8 + 8) {
            #pragma unroll
            for (int i = 0; i < 4; i++) {
                int ql = (ty - pass * 8) * 4 + i;
                #pragma unroll
                for (int t = 0; t < KTOP; t++) {
                    mbv[ql][tx * KTOP + t] = lv[i][t];
                    mbi[ql][tx * KTOP + t] = li[i][t];
                }
            }
        }
        __syncthreads();
        if (tid < 32) {
            int ql = tid;
            int q  = qBase + pass * 32 + ql;
            float bv[KTOP]; int bi[KTOP];
            #pragma unroll
            for (int t = 0; t < KTOP; t++) { bv[t] = -FLT_MAX; bi[t] = 0x7fffffff; }
            for (int c = 0; c < 16 * KTOP; c++) {
                float s = mbv[ql][c]; int id = mbi[ql][c];
                if (better(s, id, bv[KTOP - 1], bi[KTOP - 1])) {
                    int pos = KTOP - 1;
                    while (pos > 0 && better(s, id, bv[pos - 1], bi[pos - 1])) {
                        bv[pos] = bv[pos - 1]; bi[pos] = bi[pos - 1]; pos--;
                    }
                    bv[pos] = s; bi[pos] = id;
                }
            }
            #pragma unroll
            for (int t = 0; t < KTOP; t++) {
                g_pv[(q * SCH + chunkId) * KTOP + t] = bv[t];
                g_pi[(q * SCH + chunkId) * KTOP + t] = bi[t];
            }
        }
    }
}

// ---------------- kernel 3: global top-7 merge ----------------
__global__ void merge_topk_kernel() {
    int q = blockIdx.x * blockDim.x + threadIdx.x;
    if (q >= NQ) return;
    float bv[KTOP]; int bi[KTOP];
    #pragma unroll
    for (int t = 0; t < KTOP; t++) { bv[t] = -FLT_MAX; bi[t] = 0x7fffffff; }
    const float* pv = g_pv + q * SCH * KTOP;
    const int*   pi = g_pi + q * SCH * KTOP;
    for (int c = 0; c < SCH * KTOP; c++) {
        float s = pv[c]; int id = pi[c];
        if (better(s, id, bv[KTOP - 1], bi[KTOP - 1])) {
            int pos = KTOP - 1;
            while (pos > 0 && better(s, id, bv[pos - 1], bi[pos - 1])) {
                bv[pos] = bv[pos - 1]; bi[pos] = bi[pos - 1]; pos--;
            }
            bv[pos] = s; bi[pos] = id;
        }
    }
    #pragma unroll
    for (int t = 0; t < KTOP; t++) g_topi[q * KTOP + t] = bi[t];
}

// ---------------- kernel 4: GCN-fused epilogue + anomaly score ----------------
__global__ __launch_bounds__(256)
void finalize_kernel(const float* __restrict__ qe,
                     const float* __restrict__ pool,
                     const float* __restrict__ W,
                     const float* __restrict__ bvec,
                     float* __restrict__ out) {
    int q = blockIdx.x;
    int d = threadIdx.x;
    __shared__ float vsh[DIM];
    __shared__ float red[3][8];

    // c_k = self_c[k] + edge_c[k] (combined chain weights), mean folded later
    const float cw0 = 1.70710678f;  // 1 + 1/sqrt(2)
    const float cw6 = 0.5f;

    float acc = 0.0f;
    #pragma unroll
    for (int k = 0; k < KTOP; k++) {
        int id = g_topi[q * KTOP + k];
        float c = (k == 0) ? cw0 : ((k == 6) ? cw6 : 1.0f);
        acc += c * pool[(size_t)id * DIM + d];
    }
    vsh[d] = acc;
    __syncthreads();

    float f = 0.0f;
    #pragma unroll 8
    for (int j = 0; j < DIM; j++) f += vsh[j] * W[j * DIM + d];
    f = f * (1.0f / 7.0f) + bvec[d];

    float qnv = g_qn[q * DIM + d];
    float qev = qe[q * DIM + d];
    float ff = f * f;
    float qf = qnv * f;
    float dd = (qev - f) * (qev - f);

    #pragma unroll
    for (int o = 16; o > 0; o >>= 1) {
        ff += __shfl_xor_sync(0xffffffff, ff, o);
        qf += __shfl_xor_sync(0xffffffff, qf, o);
        dd += __shfl_xor_sync(0xffffffff, dd, o);
    }
    int lane = d & 31, w = d >> 5;
    if (lane == 0) { red[0][w] = ff; red[1][w] = qf; red[2][w] = dd; }
    __syncthreads();
    if (d == 0) {
        float FF = 0, QF = 0, DD = 0;
        #pragma unroll
        for (int i = 0; i < 8; i++) { FF += red[0][i]; QF += red[1][i]; DD += red[2][i]; }
        float nf  = sqrtf(FF);
        float cosv = QF / fmaxf(nf, 1e-8f);
        out[q] = 0.6f * (1.0f - cosv) + 0.4f * sqrtf(DD);
    }
}

// ---------------- launcher ----------------
extern "C" void kernel_launch(void* const* d_in, const int* in_sizes, int n_in,
                              void* d_out, int out_size) {
    const float* qe  = (const float*)d_in[0];
    const float* qt  = (const float*)d_in[1];
    const float* pe  = (const float*)d_in[2];
    const float* pt  = (const float*)d_in[3];
    const float* lam = (const float*)d_in[4];
    const float* W   = (const float*)d_in[5];
    const float* b   = (const float*)d_in[6];
    float* out = (float*)d_out;

    prep_query_kernel<<<NQ / 8, 256>>>(qe, qt, lam);
    prep_pool_kernel<<<(MP + 7) / 8, 256>>>(pe, pt, lam);
    dim3 grid(NQ / QB, SCH);
    main_topk_kernel<<<grid, 256>>>(pe);
    merge_topk_kernel<<<(NQ + 255) / 256, 256>>>();
    finalize_kernel<<<NQ, 256>>>(qe, pe, W, b, out);
}

// round 2
// speedup vs baseline: 1.6651x; 1.6651x over previous
#include <cuda_runtime.h>
#include <math.h>
#include <float.h>

#define NQ    1024
#define MP    100000
#define DIM   256
#define KTOP  7
#define QTILE 128
#define PTILE 256
#define DKc   8
#define NTILES 391          // ceil(100000/256), padded pool index space = 100096
#define TPC   22            // tiles per chunk
#define NCH   18            // chunks: 17*22 + 17 = 391
#define MPPAD (NTILES*PTILE)

// ---------------- scratch (no allocations allowed) ----------------
__device__ float g_qn[NQ * DIM];     // normalized queries
__device__ float g_eq[NQ];           // exp(+lambda*qt)
__device__ float g_ieq[NQ];          // exp(-lambda*qt)
__device__ float g_pA[MPPAD];        // pinv * exp(-lambda*pt)
__device__ float g_pB[MPPAD];        // pinv * exp(+lambda*pt)
__device__ float g_pv[NQ * NCH * KTOP];
__device__ int   g_pi[NQ * NCH * KTOP];
__device__ int   g_topi[NQ * KTOP];

__device__ __forceinline__ bool better(float s1, int i1, float s2, int i2) {
    // jax.lax.top_k ordering: higher score first; tie -> lower index
    return (s1 > s2) || (s1 == s2 && i1 < i2);
}

// f32x2 helpers (sm_100+ packed fp32)
__device__ __forceinline__ unsigned long long pk2(float x) {
    unsigned long long r;
    asm("mov.b64 %0, {%1, %1};" : "=l"(r) : "f"(x));
    return r;
}
__device__ __forceinline__ void fma2(unsigned long long &d, unsigned long long a, unsigned long long b) {
    asm("fma.rn.f32x2 %0, %1, %2, %0;" : "+l"(d) : "l"(a), "l"(b));
}
__device__ __forceinline__ float2 up2(unsigned long long v) {
    float2 r;
    asm("mov.b64 {%0, %1}, %2;" : "=f"(r.x), "=f"(r.y) : "l"(v));
    return r;
}

// ---------------- kernel 0: query prep ----------------
__global__ void prep_query_kernel(const float* __restrict__ qe,
                                  const float* __restrict__ qt,
                                  const float* __restrict__ lam) {
    int row  = blockIdx.x * 8 + (threadIdx.x >> 5);
    int lane = threadIdx.x & 31;
    if (row >= NQ) return;
    const float4* src = (const float4*)(qe + row * DIM + lane * 8);
    float4 a = src[0], b = src[1];
    float ss = a.x*a.x + a.y*a.y + a.z*a.z + a.w*a.w
             + b.x*b.x + b.y*b.y + b.z*b.z + b.w*b.w;
    #pragma unroll
    for (int o = 16; o > 0; o >>= 1) ss += __shfl_xor_sync(0xffffffff, ss, o);
    float inv = 1.0f / fmaxf(sqrtf(ss), 1e-8f);
    float4* dst = (float4*)(g_qn + row * DIM + lane * 8);
    a.x *= inv; a.y *= inv; a.z *= inv; a.w *= inv;
    b.x *= inv; b.y *= inv; b.z *= inv; b.w *= inv;
    dst[0] = a; dst[1] = b;
    if (lane == 0) {
        float l = lam[0];
        float t = qt[row];
        g_eq[row]  = expf(l * t);
        g_ieq[row] = expf(-l * t);
    }
}

// ---------------- kernel 1: pool prep ----------------
__global__ void prep_pool_kernel(const float* __restrict__ pe,
                                 const float* __restrict__ pt,
                                 const float* __restrict__ lam) {
    int row  = blockIdx.x * 8 + (threadIdx.x >> 5);
    int lane = threadIdx.x & 31;
    if (row >= MP) return;
    const float4* src = (const float4*)(pe + row * DIM + lane * 8);
    float4 a = src[0], b = src[1];
    float ss = a.x*a.x + a.y*a.y + a.z*a.z + a.w*a.w
             + b.x*b.x + b.y*b.y + b.z*b.z + b.w*b.w;
    #pragma unroll
    for (int o = 16; o > 0; o >>= 1) ss += __shfl_xor_sync(0xffffffff, ss, o);
    if (lane == 0) {
        float inv = 1.0f / fmaxf(sqrtf(ss), 1e-8f);
        float l = lam[0];
        float t = pt[row];
        g_pA[row] = inv * expf(-l * t);
        g_pB[row] = inv * expf(l * t);
    }
}

// ---------------- kernel 2: fused f32x2 GEMM + streaming top-7 ----------------
__global__ __launch_bounds__(256, 1)
void main_topk_kernel(const float* __restrict__ pool) {
    __shared__ __align__(16) float qs[2][DKc][QTILE];
    __shared__ __align__(16) float ps[2][DKc][PTILE];
    __shared__ float seq[QTILE], sieq[QTILE];
    __shared__ float smv[32][16 * KTOP];
    __shared__ int   smi[32][16 * KTOP];

    const int tid = threadIdx.x;
    const int tx  = tid & 15;          // pool direction
    const int ty  = tid >> 4;          // query direction
    const int qBase = blockIdx.x * QTILE;
    const int ch    = blockIdx.y;
    const int tile0   = ch * TPC;
    const int tileEnd = min(tile0 + TPC, NTILES);

    if (tid < QTILE) { seq[tid] = g_eq[qBase + tid]; sieq[tid] = g_ieq[qBase + tid]; }
    __syncthreads();

    // per-thread top-7 (8 queries each); hot path only touches lminv/lmini
    float lv[8][KTOP]; int li[8][KTOP];
    float lminv[8]; int lmini[8]; int lslot[8];
    #pragma unroll
    for (int i = 0; i < 8; i++) {
        #pragma unroll
        for (int t = 0; t < KTOP; t++) { lv[i][t] = -FLT_MAX; li[i][t] = 0x7fffffff; }
        lminv[i] = -FLT_MAX; lmini[i] = 0x7fffffff; lslot[i] = 0;
    }

    const int qoff = (tid & 1) * 4;
    const float* qptr = g_qn + (size_t)(qBase + (tid >> 1)) * DIM + qoff;

    for (int t = tile0; t < tileEnd; t++) {
        const int pBase = t * PTILE;
        const float* pptr = pool + (size_t)min(pBase + tid, MP - 1) * DIM;

        unsigned long long acc[8][8];
        #pragma unroll
        for (int i = 0; i < 8; i++)
            #pragma unroll
            for (int j = 0; j < 8; j++) acc[i][j] = 0ULL;

        // ---- prologue: stage step 0 into buffer 0 ----
        {
            float4 qv  = *(const float4*)qptr;
            float4 pv0 = *(const float4*)(pptr);
            float4 pv1 = *(const float4*)(pptr + 4);
            int q = tid >> 1;
            qs[0][qoff + 0][q] = qv.x; qs[0][qoff + 1][q] = qv.y;
            qs[0][qoff + 2][q] = qv.z; qs[0][qoff + 3][q] = qv.w;
            ps[0][0][tid] = pv0.x; ps[0][1][tid] = pv0.y;
            ps[0][2][tid] = pv0.z; ps[0][3][tid] = pv0.w;
            ps[0][4][tid] = pv1.x; ps[0][5][tid] = pv1.y;
            ps[0][6][tid] = pv1.z; ps[0][7][tid] = pv1.w;
        }
        __syncthreads();

        #pragma unroll 1
        for (int s = 0; s < DIM / DKc; s++) {
            const int cur = s & 1;
            float4 qn_n, p0_n, p1_n;
            const bool more = (s + 1 < DIM / DKc);
            if (more) {
                int d0 = (s + 1) * DKc;
                qn_n = *(const float4*)(qptr + d0);
                p0_n = *(const float4*)(pptr + d0);
                p1_n = *(const float4*)(pptr + d0 + 4);
            }
            #pragma unroll
            for (int kk = 0; kk < DKc; kk++) {
                ulonglong2 b0 = *(const ulonglong2*)&ps[cur][kk][tx * 4];
                ulonglong2 b1 = *(const ulonglong2*)&ps[cur][kk][64 + tx * 4];
                ulonglong2 b2 = *(const ulonglong2*)&ps[cur][kk][128 + tx * 4];
                ulonglong2 b3 = *(const ulonglong2*)&ps[cur][kk][192 + tx * 4];
                float4 al = *(const float4*)&qs[cur][kk][ty * 8];
                float4 ah = *(const float4*)&qs[cur][kk][ty * 8 + 4];
                float av[8] = {al.x, al.y, al.z, al.w, ah.x, ah.y, ah.z, ah.w};
                #pragma unroll
                for (int i = 0; i < 8; i++) {
                    unsigned long long ap = pk2(av[i]);
                    fma2(acc[i][0], ap, b0.x); fma2(acc[i][1], ap, b0.y);
                    fma2(acc[i][2], ap, b1.x); fma2(acc[i][3], ap, b1.y);
                    fma2(acc[i][4], ap, b2.x); fma2(acc[i][5], ap, b2.y);
                    fma2(acc[i][6], ap, b3.x); fma2(acc[i][7], ap, b3.y);
                }
            }
            if (more) {
                const int nb = cur ^ 1;
                int q = tid >> 1;
                qs[nb][qoff + 0][q] = qn_n.x; qs[nb][qoff + 1][q] = qn_n.y;
                qs[nb][qoff + 2][q] = qn_n.z; qs[nb][qoff + 3][q] = qn_n.w;
                ps[nb][0][tid] = p0_n.x; ps[nb][1][tid] = p0_n.y;
                ps[nb][2][tid] = p0_n.z; ps[nb][3][tid] = p0_n.w;
                ps[nb][4][tid] = p1_n.x; ps[nb][5][tid] = p1_n.y;
                ps[nb][6][tid] = p1_n.z; ps[nb][7][tid] = p1_n.w;
            }
            __syncthreads();
        }

        // ---- epilogue: time-weight + streaming top-7 ----
        float Aall[16], Ball[16];
        #pragma unroll
        for (int c = 0; c < 4; c++) {
            int p0 = pBase + c * 64 + tx * 4;
            float4 A = *(const float4*)&g_pA[p0];
            float4 B = *(const float4*)&g_pB[p0];
            Aall[c*4+0] = A.x; Aall[c*4+1] = A.y; Aall[c*4+2] = A.z; Aall[c*4+3] = A.w;
            Ball[c*4+0] = B.x; Ball[c*4+1] = B.y; Ball[c*4+2] = B.z; Ball[c*4+3] = B.w;
        }
        #pragma unroll
        for (int i = 0; i < 8; i++) {
            float eq  = seq[ty * 8 + i];
            float ieq = sieq[ty * 8 + i];
            #pragma unroll
            for (int c = 0; c < 4; c++) {
                float2 s01 = up2(acc[i][c * 2]);
                float2 s23 = up2(acc[i][c * 2 + 1]);
                float sv4[4] = {s01.x, s01.y, s23.x, s23.y};
                int p0 = pBase + c * 64 + tx * 4;
                #pragma unroll
                for (int e = 0; e < 4; e++) {
                    int p = p0 + e;
                    float s = sv4[e] * fminf(eq * Aall[c*4+e], ieq * Ball[c*4+e]);
                    if (p < MP && better(s, p, lminv[i], lmini[i])) {
                        lv[i][lslot[i]] = s; li[i][lslot[i]] = p;
                        float mvv = lv[i][0]; int mii = li[i][0]; int ms = 0;
                        #pragma unroll
                        for (int t2 = 1; t2 < KTOP; t2++) {
                            if (better(mvv, mii, lv[i][t2], li[i][t2])) {
                                mvv = lv[i][t2]; mii = li[i][t2]; ms = t2;
                            }
                        }
                        lminv[i] = mvv; lmini[i] = mii; lslot[i] = ms;
                    }
                }
            }
        }
    }

    // ---- merge 16 per-thread lists per query -> sorted top-7 per (q, chunk) ----
    for (int pass = 0; pass < 4; pass++) {
        __syncthreads();
        if (ty >= pass * 4 && ty < pass * 4 + 4) {
            #pragma unroll
            for (int i = 0; i < 8; i++) {
                int row = (ty - pass * 4) * 8 + i;
                #pragma unroll
                for (int t2 = 0; t2 < KTOP; t2++) {
                    smv[row][tx * KTOP + t2] = lv[i][t2];
                    smi[row][tx * KTOP + t2] = li[i][t2];
                }
            }
        }
        __syncthreads();
        if (tid < 32) {
            int q = qBase + pass * 32 + tid;
            float bv[KTOP]; int bi[KTOP];
            #pragma unroll
            for (int t2 = 0; t2 < KTOP; t2++) { bv[t2] = -FLT_MAX; bi[t2] = 0x7fffffff; }
            for (int c2 = 0; c2 < 16 * KTOP; c2++) {
                float sc = smv[tid][c2]; int id = smi[tid][c2];
                if (better(sc, id, bv[KTOP - 1], bi[KTOP - 1])) {
                    int pos = KTOP - 1;
                    while (pos > 0 && better(sc, id, bv[pos - 1], bi[pos - 1])) {
                        bv[pos] = bv[pos - 1]; bi[pos] = bi[pos - 1]; pos--;
                    }
                    bv[pos] = sc; bi[pos] = id;
                }
            }
            #pragma unroll
            for (int t2 = 0; t2 < KTOP; t2++) {
                g_pv[(q * NCH + ch) * KTOP + t2] = bv[t2];
                g_pi[(q * NCH + ch) * KTOP + t2] = bi[t2];
            }
        }
    }
}

// ---------------- kernel 3: global top-7 merge (warp per query) ----------------
__global__ void merge_topk_kernel() {
    __shared__ float sv[4][NCH * KTOP];
    __shared__ int   si[4][NCH * KTOP];
    const int w = threadIdx.x >> 5, lane = threadIdx.x & 31;
    const int q = blockIdx.x * 4 + w;
    const int TOT = NCH * KTOP;  // 126
    for (int c = lane; c < TOT; c += 32) {
        sv[w][c] = g_pv[q * TOT + c];
        si[w][c] = g_pi[q * TOT + c];
    }
    __syncwarp();
    if (lane == 0) {
        float bv[KTOP]; int bi[KTOP];
        #pragma unroll
        for (int t = 0; t < KTOP; t++) { bv[t] = -FLT_MAX; bi[t] = 0x7fffffff; }
        for (int c = 0; c < TOT; c++) {
            float s = sv[w][c]; int id = si[w][c];
            if (better(s, id, bv[KTOP - 1], bi[KTOP - 1])) {
                int pos = KTOP - 1;
                while (pos > 0 && better(s, id, bv[pos - 1], bi[pos - 1])) {
                    bv[pos] = bv[pos - 1]; bi[pos] = bi[pos - 1]; pos--;
                }
                bv[pos] = s; bi[pos] = id;
            }
        }
        #pragma unroll
        for (int t = 0; t < KTOP; t++) g_topi[q * KTOP + t] = bi[t];
    }
}

// ---------------- kernel 4: GCN-fused epilogue + anomaly score ----------------
__global__ __launch_bounds__(256)
void finalize_kernel(const float* __restrict__ qe,
                     const float* __restrict__ pool,
                     const float* __restrict__ W,
                     const float* __restrict__ bvec,
                     float* __restrict__ out) {
    int q = blockIdx.x;
    int d = threadIdx.x;
    __shared__ float vsh[DIM];
    __shared__ float red[3][8];

    const float cw0 = 1.70710678f;  // 1 + 1/sqrt(2)
    const float cw6 = 0.5f;

    float acc = 0.0f;
    #pragma unroll
    for (int k = 0; k < KTOP; k++) {
        int id = g_topi[q * KTOP + k];
        float c = (k == 0) ? cw0 : ((k == 6) ? cw6 : 1.0f);
        acc += c * pool[(size_t)id * DIM + d];
    }
    vsh[d] = acc;
    __syncthreads();

    float f = 0.0f;
    #pragma unroll 8
    for (int j = 0; j < DIM; j++) f += vsh[j] * W[j * DIM + d];
    f = f * (1.0f / 7.0f) + bvec[d];

    float qnv = g_qn[q * DIM + d];
    float qev = qe[q * DIM + d];
    float ff = f * f;
    float qf = qnv * f;
    float dd = (qev - f) * (qev - f);

    #pragma unroll
    for (int o = 16; o > 0; o >>= 1) {
        ff += __shfl_xor_sync(0xffffffff, ff, o);
        qf += __shfl_xor_sync(0xffffffff, qf, o);
        dd += __shfl_xor_sync(0xffffffff, dd, o);
    }
    int lane = d & 31, w = d >> 5;
    if (lane == 0) { red[0][w] = ff; red[1][w] = qf; red[2][w] = dd; }
    __syncthreads();
    if (d == 0) {
        float FF = 0, QF = 0, DD = 0;
        #pragma unroll
        for (int i = 0; i < 8; i++) { FF += red[0][i]; QF += red[1][i]; DD += red[2][i]; }
        float nf   = sqrtf(FF);
        float cosv = QF / fmaxf(nf, 1e-8f);
        out[q] = 0.6f * (1.0f - cosv) + 0.4f * sqrtf(DD);
    }
}

// ---------------- launcher ----------------
extern "C" void kernel_launch(void* const* d_in, const int* in_sizes, int n_in,
                              void* d_out, int out_size) {
    const float* qe  = (const float*)d_in[0];
    const float* qt  = (const float*)d_in[1];
    const float* pe  = (const float*)d_in[2];
    const float* pt  = (const float*)d_in[3];
    const float* lam = (const float*)d_in[4];
    const float* W   = (const float*)d_in[5];
    const float* b   = (const float*)d_in[6];
    float* out = (float*)d_out;

    prep_query_kernel<<<NQ / 8, 256>>>(qe, qt, lam);
    prep_pool_kernel<<<(MP + 7) / 8, 256>>>(pe, pt, lam);
    dim3 grid(NQ / QTILE, NCH);
    main_topk_kernel<<<grid, 256>>>(pe);
    merge_topk_kernel<<<NQ / 4, 128>>>();
    finalize_kernel<<<NQ, 256>>>(qe, pe, W, b, out);
}

// round 4
// speedup vs baseline: 3.2475x; 1.9503x over previous
#include <cuda_runtime.h>
#include <cuda_bf16.h>
#include <math.h>
#include <float.h>
#include <stdint.h>

#define NQ    1024
#define MP    100000
#define DIM   256
#define KTOP  7
#define QTILE 128
#define PTILE 128
#define NT    782            // ceil(100000/128)
#define TPC   44             // tiles per chunk
#define NCH   18             // 17*44 + 34 = 782
#define KC    12             // candidates kept per (q, chunk)
#define MPPAD (NT*PTILE)     // 100096

// ---------------- device scratch ----------------
__device__ float g_qn[NQ * DIM];
__device__ float g_eq[NQ];
__device__ float g_ieq[NQ];
__device__ float g_pA[MPPAD];   // pinv * exp(-l*pt)
__device__ float g_pB[MPPAD];   // pinv * exp(+l*pt)
__device__ __nv_bfloat16 g_qhi[NQ * DIM];
__device__ __nv_bfloat16 g_phi[(size_t)MPPAD * DIM];
__device__ int   g_ci[(size_t)NQ * NCH * KC];
__device__ int   g_topi[NQ * KTOP];

__device__ __forceinline__ bool better(float s1, int i1, float s2, int i2) {
    return (s1 > s2) || (s1 == s2 && i1 < i2);
}

__device__ __forceinline__ uint32_t smem_to_u32(const void* p) {
    uint32_t a;
    asm("{ .reg .u64 t; cvta.to.shared.u64 t, %1; cvt.u32.u64 %0, t; }" : "=r"(a) : "l"(p));
    return a;
}
__device__ __forceinline__ void ldsm_x4(uint32_t& r0, uint32_t& r1, uint32_t& r2, uint32_t& r3,
                                        uint32_t addr) {
    asm volatile("ldmatrix.sync.aligned.m8n8.x4.shared.b16 {%0,%1,%2,%3}, [%4];"
        : "=r"(r0), "=r"(r1), "=r"(r2), "=r"(r3) : "r"(addr));
}
__device__ __forceinline__ void mma16816(float* d, const uint32_t* a, uint32_t b0, uint32_t b1) {
    asm volatile("mma.sync.aligned.m16n8k16.row.col.f32.bf16.bf16.f32 "
        "{%0,%1,%2,%3}, {%4,%5,%6,%7}, {%8,%9}, {%0,%1,%2,%3};"
        : "+f"(d[0]), "+f"(d[1]), "+f"(d[2]), "+f"(d[3])
        : "r"(a[0]), "r"(a[1]), "r"(a[2]), "r"(a[3]), "r"(b0), "r"(b1));
}
#define CP_ASYNC16(dst, src) asm volatile("cp.async.cg.shared.global [%0], [%1], 16;" :: "r"(dst), "l"(src))
#define CP_COMMIT() asm volatile("cp.async.commit_group;" ::: "memory")
#define CP_WAIT1()  asm volatile("cp.async.wait_group 1;" ::: "memory")
#define CP_WAIT0()  asm volatile("cp.async.wait_group 0;" ::: "memory")

// smem layout
#define SOFF_A   0                     // 65536: A tile 128x256 bf16, swizzled (512B rows)
#define SOFF_B0  65536                 // 32768: B half-tile 128x128 bf16 (256B rows)
#define SOFF_B1  98304                 // 32768
#define SOFF_SC  131072                // 67584: scores 128 x 132 f32
#define SOFF_PA  198656                // 512
#define SOFF_PB  199168                // 512
#define SOFF_EQ  199680                // 1024
#define SMEM_TOTAL 200704

// ---------------- kernel 0: query prep ----------------
__global__ void prep_query_kernel(const float* __restrict__ qe,
                                  const float* __restrict__ qt,
                                  const float* __restrict__ lam) {
    int row  = blockIdx.x * 8 + (threadIdx.x >> 5);
    int lane = threadIdx.x & 31;
    if (row >= NQ) return;
    const float4* src = (const float4*)(qe + row * DIM + lane * 8);
    float4 a = src[0], b = src[1];
    float ss = a.x*a.x + a.y*a.y + a.z*a.z + a.w*a.w
             + b.x*b.x + b.y*b.y + b.z*b.z + b.w*b.w;
    #pragma unroll
    for (int o = 16; o > 0; o >>= 1) ss += __shfl_xor_sync(0xffffffff, ss, o);
    float inv = 1.0f / fmaxf(sqrtf(ss), 1e-8f);
    float v[8] = {a.x*inv, a.y*inv, a.z*inv, a.w*inv, b.x*inv, b.y*inv, b.z*inv, b.w*inv};
    float4* dst = (float4*)(g_qn + row * DIM + lane * 8);
    dst[0] = make_float4(v[0], v[1], v[2], v[3]);
    dst[1] = make_float4(v[4], v[5], v[6], v[7]);
    __nv_bfloat16 hv[8];
    #pragma unroll
    for (int i = 0; i < 8; i++) hv[i] = __float2bfloat16(v[i]);
    *(uint4*)(g_qhi + row * DIM + lane * 8) = *(uint4*)hv;
    if (lane == 0) {
        float l = lam[0], t = qt[row];
        g_eq[row]  = expf(l * t);
        g_ieq[row] = expf(-l * t);
    }
}

// ---------------- kernel 1: pool prep ----------------
__global__ void prep_pool_kernel(const float* __restrict__ pe,
                                 const float* __restrict__ pt,
                                 const float* __restrict__ lam) {
    int row  = blockIdx.x * 8 + (threadIdx.x >> 5);
    int lane = threadIdx.x & 31;
    if (row >= MPPAD) return;
    if (row >= MP) {
        *(uint4*)(g_phi + (size_t)row * DIM + lane * 8) = make_uint4(0, 0, 0, 0);
        if (lane == 0) { g_pA[row] = 0.f; g_pB[row] = 0.f; }
        return;
    }
    const float4* src = (const float4*)(pe + (size_t)row * DIM + lane * 8);
    float4 a = src[0], b = src[1];
    float ss = a.x*a.x + a.y*a.y + a.z*a.z + a.w*a.w
             + b.x*b.x + b.y*b.y + b.z*b.z + b.w*b.w;
    #pragma unroll
    for (int o = 16; o > 0; o >>= 1) ss += __shfl_xor_sync(0xffffffff, ss, o);
    float v[8] = {a.x, a.y, a.z, a.w, b.x, b.y, b.z, b.w};
    __nv_bfloat16 hv[8];
    #pragma unroll
    for (int i = 0; i < 8; i++) hv[i] = __float2bfloat16(v[i]);
    *(uint4*)(g_phi + (size_t)row * DIM + lane * 8) = *(uint4*)hv;
    if (lane == 0) {
        float inv = 1.0f / fmaxf(sqrtf(ss), 1e-8f);
        float l = lam[0], t = pt[row];
        g_pA[row] = inv * expf(-l * t);
        g_pB[row] = inv * expf(l * t);
    }
}

// ---------------- kernel 2: HMMA bf16 GEMM + approx top-12 ----------------
__global__ __launch_bounds__(256, 1)
void main_topk_kernel() {
    extern __shared__ char smem[];
    const uint32_t sb = smem_to_u32(smem);
    float* sc   = (float*)(smem + SOFF_SC);
    float* spA  = (float*)(smem + SOFF_PA);
    float* spB  = (float*)(smem + SOFF_PB);
    float* seq  = (float*)(smem + SOFF_EQ);
    float* sieq = (float*)(smem + SOFF_EQ + 512);

    const int tid = threadIdx.x;
    const int wid = tid >> 5, lane = tid & 31;
    const int wq = wid & 3, wp = wid >> 2;
    const int qBase = blockIdx.x * QTILE;
    const int ch = blockIdx.y;
    const int tile0 = ch * TPC;
    const int tileEnd = min(tile0 + TPC, NT);
    const int H = (tileEnd - tile0) * 2;

    // load A tile (bf16 queries, swizzled 512B rows) + eq/ieq
    {
        int row = tid >> 1, half = tid & 1;
        const uint4* src = (const uint4*)(g_qhi + (size_t)(qBase + row) * DIM) + half * 16;
        uint32_t rb = (uint32_t)row * 512;
        uint32_t xr0 = (uint32_t)(row & 7) << 4;
        #pragma unroll
        for (int g = 0; g < 16; g++) {
            uint32_t kg = half * 16 + g;
            *(uint4*)(smem + SOFF_A + rb + ((kg << 4) ^ xr0)) = src[g];
        }
        if (tid < 128) { seq[tid] = g_eq[qBase + tid]; sieq[tid] = g_ieq[qBase + tid]; }
    }

    // streaming top-12 state (this thread owns one (row, col-half))
    float lv[KC]; int li[KC];
    float lminv = -FLT_MAX; int lmini = 0x7fffffff; int lslot = 0;
    #pragma unroll
    for (int t = 0; t < KC; t++) { lv[t] = -FLT_MAX; li[t] = 0x7fffffff; }

    // fragment addressing
    const int mh = (lane >> 4) & 1;        // matrix-pair selector (k half of 16B granule pair)
    const int mlow = (lane >> 3) & 1;      // row +8 selector
    const int lr = lane & 7;
    const uint32_t xr = (uint32_t)lr << 4;
    uint32_t aBase[2], bBase[4];
    #pragma unroll
    for (int mt = 0; mt < 2; mt++)
        aBase[mt] = sb + SOFF_A + (uint32_t)(wq * 32 + mt * 16 + mlow * 8 + lr) * 512;
    #pragma unroll
    for (int n16 = 0; n16 < 4; n16++)
        bBase[n16] = (uint32_t)(wp * 64 + n16 * 16 + mlow * 8 + lr) * 256;

    // cp.async of B half-tile s (tile tile0+s/2, k-half s&1)
    const int brow = tid >> 1, bhalf = tid & 1;
    const uint32_t brb = (uint32_t)brow * 256;
    const uint32_t bxr = (uint32_t)(brow & 7) << 4;
    #define ISSUE_HALF(s_) do { \
        int _t = tile0 + ((s_) >> 1), _kh = (s_) & 1; \
        const char* _src = (const char*)(g_phi + (size_t)(_t * PTILE + brow) * DIM + _kh * 128) + bhalf * 128; \
        uint32_t _dst = sb + (((s_) & 1) ? SOFF_B1 : SOFF_B0); \
        _Pragma("unroll") \
        for (int _g = 0; _g < 8; _g++) { \
            uint32_t _kg = bhalf * 8 + _g; \
            CP_ASYNC16(_dst + brb + ((_kg << 4) ^ bxr), _src + _g * 16); \
        } \
        CP_COMMIT(); \
    } while (0)

    ISSUE_HALF(0);
    int s = 0;
    float d[2][8][4];

    #pragma unroll 1
    for (int t = tile0; t < tileEnd; t++) {
        const int pBase = t * PTILE;
        #pragma unroll
        for (int mt = 0; mt < 2; mt++)
            #pragma unroll
            for (int n = 0; n < 8; n++)
                #pragma unroll
                for (int e = 0; e < 4; e++) d[mt][n][e] = 0.0f;

        #pragma unroll 1
        for (int h = 0; h < 2; h++) {
            if (s + 1 < H) { ISSUE_HALF(s + 1); CP_WAIT1(); } else { CP_WAIT0(); }
            __syncthreads();
            const uint32_t bBuf = sb + ((s & 1) ? SOFF_B1 : SOFF_B0);
            #pragma unroll
            for (int ks2 = 0; ks2 < 8; ks2++) {
                const int ks = h * 8 + ks2;
                uint32_t a[2][4];
                uint32_t aoffk = ((uint32_t)((ks * 2 + mh) << 4)) ^ xr;
                ldsm_x4(a[0][0], a[0][1], a[0][2], a[0][3], aBase[0] + aoffk);
                ldsm_x4(a[1][0], a[1][1], a[1][2], a[1][3], aBase[1] + aoffk);
                uint32_t b[4][4];
                uint32_t boffk = ((uint32_t)((ks2 * 2 + mh) << 4)) ^ xr;
                #pragma unroll
                for (int n16 = 0; n16 < 4; n16++)
                    ldsm_x4(b[n16][0], b[n16][1], b[n16][2], b[n16][3],
                            bBuf + bBase[n16] + boffk);
                #pragma unroll
                for (int mt = 0; mt < 2; mt++)
                    #pragma unroll
                    for (int n16 = 0; n16 < 4; n16++) {
                        mma16816(d[mt][n16 * 2 + 0], a[mt], b[n16][0], b[n16][2]);
                        mma16816(d[mt][n16 * 2 + 1], a[mt], b[n16][1], b[n16][3]);
                    }
            }
            __syncthreads();
            s++;
        }

        // epilogue: dump weighted-ready scores, then per-row scan
        {
            int g = lane >> 2, i2 = (lane & 3) * 2;
            #pragma unroll
            for (int mt = 0; mt < 2; mt++) {
                int r0 = wq * 32 + mt * 16 + g;
                #pragma unroll
                for (int n = 0; n < 8; n++) {
                    int c0 = wp * 64 + n * 8 + i2;
                    *(float2*)&sc[r0 * 132 + c0]       = make_float2(d[mt][n][0], d[mt][n][1]);
                    *(float2*)&sc[(r0 + 8) * 132 + c0] = make_float2(d[mt][n][2], d[mt][n][3]);
                }
            }
            if (tid < 128) spA[tid] = g_pA[pBase + tid];
            else           spB[tid - 128] = g_pB[pBase + tid - 128];
            __syncthreads();

            int row = tid >> 1, half = tid & 1;
            float eqv = seq[row], ieqv = sieq[row];
            const float4* scv = (const float4*)&sc[row * 132 + half * 64];
            const float4* pav = (const float4*)&spA[half * 64];
            const float4* pbv = (const float4*)&spB[half * 64];
            int p0 = pBase + half * 64;
            #pragma unroll 4
            for (int iv = 0; iv < 16; iv++) {
                float4 dv = scv[iv], pa = pav[iv], pb = pbv[iv];
                float sv[4];
                sv[0] = dv.x * fminf(eqv * pa.x, ieqv * pb.x);
                sv[1] = dv.y * fminf(eqv * pa.y, ieqv * pb.y);
                sv[2] = dv.z * fminf(eqv * pa.z, ieqv * pb.z);
                sv[3] = dv.w * fminf(eqv * pa.w, ieqv * pb.w);
                #pragma unroll
                for (int e = 0; e < 4; e++) {
                    int p = p0 + iv * 4 + e;
                    if (p < MP && better(sv[e], p, lminv, lmini)) {
                        lv[lslot] = sv[e]; li[lslot] = p;
                        float mv = lv[0]; int mi = li[0]; int ms = 0;
                        #pragma unroll
                        for (int u = 1; u < KC; u++)
                            if (better(mv, mi, lv[u], li[u])) { mv = lv[u]; mi = li[u]; ms = u; }
                        lminv = mv; lmini = mi; lslot = ms;
                    }
                }
            }
        }
    }

    // merge the 2 half-lists per query -> top-12 indices per (q, chunk)
    __syncthreads();
    float* mv = sc;
    int*   mi = (int*)(smem + SOFF_SC + 128 * 2 * KC * 4);
    #pragma unroll
    for (int j = 0; j < KC; j++) { mv[tid * KC + j] = lv[j]; mi[tid * KC + j] = li[j]; }
    __syncthreads();
    if (tid < 128) {
        float bv[KC]; int bi[KC];
        #pragma unroll
        for (int j = 0; j < KC; j++) { bv[j] = -FLT_MAX; bi[j] = 0x7fffffff; }
        for (int c = 0; c < 2 * KC; c++) {
            float s2 = mv[tid * 2 * KC + c]; int id = mi[tid * 2 * KC + c];
            if (better(s2, id, bv[KC - 1], bi[KC - 1])) {
                int pos = KC - 1;
                while (pos > 0 && better(s2, id, bv[pos - 1], bi[pos - 1])) {
                    bv[pos] = bv[pos - 1]; bi[pos] = bi[pos - 1]; pos--;
                }
                bv[pos] = s2; bi[pos] = id;
            }
        }
        size_t base = ((size_t)(qBase + tid) * NCH + ch) * KC;
        #pragma unroll
        for (int j = 0; j < KC; j++) g_ci[base + j] = bi[j];
    }
}

// ---------------- kernel 3: exact fp32 rescore of 216 candidates/query ----------------
__global__ __launch_bounds__(256)
void rescore_kernel(const float* __restrict__ pe) {
    __shared__ float qs[DIM];
    __shared__ float sc2[NCH * KC];
    __shared__ int   ci2[NCH * KC];
    const int q = blockIdx.x;
    const int tid = threadIdx.x, wid = tid >> 5, lane = tid & 31;
    qs[tid] = g_qn[q * DIM + tid];
    __syncthreads();
    const float eqv = g_eq[q], ieqv = g_ieq[q];
    for (int c = wid; c < NCH * KC; c += 8) {
        int idx = g_ci[(size_t)q * NCH * KC + c];
        float s = -FLT_MAX;
        if (idx < MP) {
            const float4* pp = (const float4*)(pe + (size_t)idx * DIM) + lane * 2;
            const float4* qq = (const float4*)qs + lane * 2;
            float4 v0 = pp[0], v1 = pp[1], q0 = qq[0], q1 = qq[1];
            float acc = v0.x*q0.x + v0.y*q0.y + v0.z*q0.z + v0.w*q0.w
                      + v1.x*q1.x + v1.y*q1.y + v1.z*q1.z + v1.w*q1.w;
            #pragma unroll
            for (int o = 16; o > 0; o >>= 1) acc += __shfl_xor_sync(0xffffffff, acc, o);
            s = acc * fminf(eqv * g_pA[idx], ieqv * g_pB[idx]);
        }
        if (lane == 0) { sc2[c] = s; ci2[c] = idx; }
    }
    __syncthreads();
    if (tid == 0) {
        float bv[KTOP]; int bi[KTOP];
        #pragma unroll
        for (int t = 0; t < KTOP; t++) { bv[t] = -FLT_MAX; bi[t] = 0x7fffffff; }
        for (int c = 0; c < NCH * KC; c++) {
            float s = sc2[c]; int id = ci2[c];
            if (id < MP && better(s, id, bv[KTOP - 1], bi[KTOP - 1])) {
                int pos = KTOP - 1;
                while (pos > 0 && better(s, id, bv[pos - 1], bi[pos - 1])) {
                    bv[pos] = bv[pos - 1]; bi[pos] = bi[pos - 1]; pos--;
                }
                bv[pos] = s; bi[pos] = id;
            }
        }
        #pragma unroll
        for (int t = 0; t < KTOP; t++) g_topi[q * KTOP + t] = bi[t];
    }
}

// ---------------- kernel 4: GCN epilogue + anomaly score ----------------
__global__ __launch_bounds__(256)
void finalize_kernel(const float* __restrict__ qe,
                     const float* __restrict__ pool,
                     const float* __restrict__ W,
                     const float* __restrict__ bvec,
                     float* __restrict__ out) {
    int q = blockIdx.x;
    int d = threadIdx.x;
    __shared__ float vsh[DIM];
    __shared__ float red[3][8];

    const float cw0 = 1.70710678f;
    const float cw6 = 0.5f;

    float acc = 0.0f;
    #pragma unroll
    for (int k = 0; k < KTOP; k++) {
        int id = g_topi[q * KTOP + k];
        float c = (k == 0) ? cw0 : ((k == 6) ? cw6 : 1.0f);
        acc += c * pool[(size_t)id * DIM + d];
    }
    vsh[d] = acc;
    __syncthreads();

    float f = 0.0f;
    #pragma unroll 8
    for (int j = 0; j < DIM; j++) f += vsh[j] * W[j * DIM + d];
    f = f * (1.0f / 7.0f) + bvec[d];

    float qnv = g_qn[q * DIM + d];
    float qev = qe[q * DIM + d];
    float ff = f * f;
    float qf = qnv * f;
    float dd = (qev - f) * (qev - f);

    #pragma unroll
    for (int o = 16; o > 0; o >>= 1) {
        ff += __shfl_xor_sync(0xffffffff, ff, o);
        qf += __shfl_xor_sync(0xffffffff, qf, o);
        dd += __shfl_xor_sync(0xffffffff, dd, o);
    }
    int lane = d & 31, w = d >> 5;
    if (lane == 0) { red[0][w] = ff; red[1][w] = qf; red[2][w] = dd; }
    __syncthreads();
    if (d == 0) {
        float FF = 0, QF = 0, DD = 0;
        #pragma unroll
        for (int i = 0; i < 8; i++) { FF += red[0][i]; QF += red[1][i]; DD += red[2][i]; }
        float nf   = sqrtf(FF);
        float cosv = QF / fmaxf(nf, 1e-8f);
        out[q] = 0.6f * (1.0f - cosv) + 0.4f * sqrtf(DD);
    }
}

// ---------------- launcher ----------------
extern "C" void kernel_launch(void* const* d_in, const int* in_sizes, int n_in,
                              void* d_out, int out_size) {
    const float* qe  = (const float*)d_in[0];
    const float* qt  = (const float*)d_in[1];
    const float* pe  = (const float*)d_in[2];
    const float* pt  = (const float*)d_in[3];
    const float* lam = (const float*)d_in[4];
    const float* W   = (const float*)d_in[5];
    const float* b   = (const float*)d_in[6];
    float* out = (float*)d_out;

    static int configured = 0;
    if (!configured) {
        cudaFuncSetAttribute(main_topk_kernel,
                             cudaFuncAttributeMaxDynamicSharedMemorySize, SMEM_TOTAL);
        configured = 1;
    }

    prep_query_kernel<<<NQ / 8, 256>>>(qe, qt, lam);
    prep_pool_kernel<<<(MPPAD + 7) / 8, 256>>>(pe, pt, lam);
    dim3 grid(NQ / QTILE, NCH);
    main_topk_kernel<<<grid, 256, SMEM_TOTAL>>>();
    rescore_kernel<<<NQ, 256>>>(pe);
    finalize_kernel<<<NQ, 256>>>(qe, pe, W, b, out);
}

// round 5
// speedup vs baseline: 5.2263x; 1.6093x over previous
#include <cuda_runtime.h>
#include <cuda_bf16.h>
#include <math.h>
#include <float.h>
#include <stdint.h>

#define NQ    1024
#define MP    100000
#define DIM   256
#define KTOP  7
#define QTILE 256
#define PTILE 128
#define NT    782            // ceil(100000/128)
#define NCH   37             // chunks; grid = 4 x 37 = 148 CTAs (one wave)
#define KC    12             // candidates per (q, chunk)
#define TOPC  28             // global approx filter size before exact rescore
#define MPPAD (NT*PTILE)     // 100096

// ---------------- device scratch ----------------
__device__ float g_qn[NQ * DIM];
__device__ float g_eq[NQ];
__device__ float g_ieq[NQ];
__device__ float g_pA[MPPAD];   // pinv * exp(-l*pt)
__device__ float g_pB[MPPAD];   // pinv * exp(+l*pt)
__device__ __nv_bfloat16 g_qhi[NQ * DIM];
__device__ __nv_bfloat16 g_phi[(size_t)MPPAD * DIM];
__device__ float g_cv[(size_t)NQ * NCH * KC];
__device__ int   g_ci[(size_t)NQ * NCH * KC];
__device__ int   g_topi[NQ * KTOP];

__device__ __forceinline__ bool better(float s1, int i1, float s2, int i2) {
    return (s1 > s2) || (s1 == s2 && i1 < i2);
}

__device__ __forceinline__ uint32_t smem_to_u32(const void* p) {
    uint32_t a;
    asm("{ .reg .u64 t; cvta.to.shared.u64 t, %1; cvt.u32.u64 %0, t; }" : "=r"(a) : "l"(p));
    return a;
}
__device__ __forceinline__ void ldsm_x4(uint32_t& r0, uint32_t& r1, uint32_t& r2, uint32_t& r3,
                                        uint32_t addr) {
    asm volatile("ldmatrix.sync.aligned.m8n8.x4.shared.b16 {%0,%1,%2,%3}, [%4];"
        : "=r"(r0), "=r"(r1), "=r"(r2), "=r"(r3) : "r"(addr));
}
__device__ __forceinline__ void mma16816(float* d, const uint32_t* a, uint32_t b0, uint32_t b1) {
    asm volatile("mma.sync.aligned.m16n8k16.row.col.f32.bf16.bf16.f32 "
        "{%0,%1,%2,%3}, {%4,%5,%6,%7}, {%8,%9}, {%0,%1,%2,%3};"
        : "+f"(d[0]), "+f"(d[1]), "+f"(d[2]), "+f"(d[3])
        : "r"(a[0]), "r"(a[1]), "r"(a[2]), "r"(a[3]), "r"(b0), "r"(b1));
}
#define CP_ASYNC16(dst, src) asm volatile("cp.async.cg.shared.global [%0], [%1], 16;" :: "r"(dst), "l"(src))
#define CP_COMMIT() asm volatile("cp.async.commit_group;" ::: "memory")
#define CP_WAIT1()  asm volatile("cp.async.wait_group 1;" ::: "memory")
#define CP_WAIT0()  asm volatile("cp.async.wait_group 0;" ::: "memory")

// top-3 sorted insertion (hot path: one compare)
__device__ __forceinline__ void ins3(float s, int p,
                                     float& v0, int& i0, float& v1, int& i1,
                                     float& v2, int& i2) {
    if (better(s, p, v2, i2)) {
        if (better(s, p, v1, i1)) {
            v2 = v1; i2 = i1;
            if (better(s, p, v0, i0)) { v1 = v0; i1 = i0; v0 = s; i0 = p; }
            else { v1 = s; i1 = p; }
        } else { v2 = s; i2 = p; }
    }
}

// smem layout
#define SOFF_A    0                  // 131072: A 256x256 bf16, swizzled 512B rows
#define SOFF_B0   131072             // 32768: B chunk 128p x 128k bf16 (256B rows)
#define SOFF_B1   163840             // 32768
#define SOFF_PAB  196608             // 1024: float2[128] = (pA, pB)
#define SMEM_TOTAL 197632

// ---------------- kernel 0: query prep ----------------
__global__ void prep_query_kernel(const float* __restrict__ qe,
                                  const float* __restrict__ qt,
                                  const float* __restrict__ lam) {
    int row  = blockIdx.x * 8 + (threadIdx.x >> 5);
    int lane = threadIdx.x & 31;
    if (row >= NQ) return;
    const float4* src = (const float4*)(qe + row * DIM + lane * 8);
    float4 a = src[0], b = src[1];
    float ss = a.x*a.x + a.y*a.y + a.z*a.z + a.w*a.w
             + b.x*b.x + b.y*b.y + b.z*b.z + b.w*b.w;
    #pragma unroll
    for (int o = 16; o > 0; o >>= 1) ss += __shfl_xor_sync(0xffffffff, ss, o);
    float inv = 1.0f / fmaxf(sqrtf(ss), 1e-8f);
    float v[8] = {a.x*inv, a.y*inv, a.z*inv, a.w*inv, b.x*inv, b.y*inv, b.z*inv, b.w*inv};
    float4* dst = (float4*)(g_qn + row * DIM + lane * 8);
    dst[0] = make_float4(v[0], v[1], v[2], v[3]);
    dst[1] = make_float4(v[4], v[5], v[6], v[7]);
    __nv_bfloat16 hv[8];
    #pragma unroll
    for (int i = 0; i < 8; i++) hv[i] = __float2bfloat16(v[i]);
    *(uint4*)(g_qhi + row * DIM + lane * 8) = *(uint4*)hv;
    if (lane == 0) {
        float l = lam[0], t = qt[row];
        g_eq[row]  = expf(l * t);
        g_ieq[row] = expf(-l * t);
    }
}

// ---------------- kernel 1: pool prep (padded to MPPAD) ----------------
__global__ void prep_pool_kernel(const float* __restrict__ pe,
                                 const float* __restrict__ pt,
                                 const float* __restrict__ lam) {
    int row  = blockIdx.x * 8 + (threadIdx.x >> 5);
    int lane = threadIdx.x & 31;
    if (row >= MPPAD) return;
    if (row >= MP) {
        *(uint4*)(g_phi + (size_t)row * DIM + lane * 8) = make_uint4(0, 0, 0, 0);
        if (lane == 0) { g_pA[row] = 0.f; g_pB[row] = 0.f; }
        return;
    }
    const float4* src = (const float4*)(pe + (size_t)row * DIM + lane * 8);
    float4 a = src[0], b = src[1];
    float ss = a.x*a.x + a.y*a.y + a.z*a.z + a.w*a.w
             + b.x*b.x + b.y*b.y + b.z*b.z + b.w*b.w;
    #pragma unroll
    for (int o = 16; o > 0; o >>= 1) ss += __shfl_xor_sync(0xffffffff, ss, o);
    float v[8] = {a.x, a.y, a.z, a.w, b.x, b.y, b.z, b.w};
    __nv_bfloat16 hv[8];
    #pragma unroll
    for (int i = 0; i < 8; i++) hv[i] = __float2bfloat16(v[i]);
    *(uint4*)(g_phi + (size_t)row * DIM + lane * 8) = *(uint4*)hv;
    if (lane == 0) {
        float inv = 1.0f / fmaxf(sqrtf(ss), 1e-8f);
        float l = lam[0], t = pt[row];
        g_pA[row] = inv * expf(-l * t);
        g_pB[row] = inv * expf(l * t);
    }
}

// ---------------- kernel 2: HMMA GEMM, in-register epilogue, bucket top-3 ----------------
__global__ __launch_bounds__(256, 1)
void main_topk_kernel() {
    extern __shared__ char smem[];
    const uint32_t sb = smem_to_u32(smem);
    float2* spAB = (float2*)(smem + SOFF_PAB);

    const int tid = threadIdx.x;
    const int wid = tid >> 5, lane = tid & 31;
    const int wq = wid >> 1, wp = wid & 1;     // 4 x 2 warps, warp tile 64q x 64p
    const int qBase = blockIdx.x * QTILE;
    const int ch = blockIdx.y;
    const int tile0   = (ch * NT) / NCH;
    const int tileEnd = ((ch + 1) * NT) / NCH;
    const int NCHK = (tileEnd - tile0) * 2;    // k-chunks total

    // ---- load A once (bf16 queries, swizzled 512B rows) ----
    {
        const uint4* asrc = (const uint4*)(g_qhi + (size_t)(qBase + tid) * DIM);
        uint32_t arb = (uint32_t)tid * 512;
        uint32_t xr0 = (uint32_t)(tid & 7) << 4;
        #pragma unroll
        for (int g = 0; g < 32; g++)
            *(uint4*)(smem + SOFF_A + arb + (((uint32_t)g << 4) ^ xr0)) = asrc[g];
    }

    // per-thread row weights (8 rows, fixed all kernel)
    const int g = lane >> 2;
    float eqr[8], ieqr[8];
    #pragma unroll
    for (int mt = 0; mt < 4; mt++)
        #pragma unroll
        for (int h = 0; h < 2; h++) {
            int r = qBase + wq * 64 + mt * 16 + g + h * 8;
            eqr[mt * 2 + h]  = g_eq[r];
            ieqr[mt * 2 + h] = g_ieq[r];
        }

    // fragment addressing
    const int mh = (lane >> 4) & 1;
    const int mlow = (lane >> 3) & 1;
    const int lr = lane & 7;
    const uint32_t xr = (uint32_t)lr << 4;
    uint32_t aBase[4], bBase[4];
    #pragma unroll
    for (int mt = 0; mt < 4; mt++)
        aBase[mt] = sb + SOFF_A + (uint32_t)(wq * 64 + mt * 16 + mlow * 8 + lr) * 512;
    #pragma unroll
    for (int n16 = 0; n16 < 4; n16++)
        bBase[n16] = (uint32_t)(wp * 64 + n16 * 16 + mlow * 8 + lr) * 256;

    // bucket top-3 per (thread, row)
    float tv0[8], tv1[8], tv2[8]; int ti0[8], ti1[8], ti2[8];
    #pragma unroll
    for (int j = 0; j < 8; j++) {
        tv0[j] = tv1[j] = tv2[j] = -FLT_MAX;
        ti0[j] = ti1[j] = ti2[j] = 0x7fffffff;
    }

    // cp.async issue for chunk s (128p x 128k = 32KB)
    const int brow = tid >> 1, bhalf = tid & 1;
    const uint32_t brb = (uint32_t)brow * 256;
    const uint32_t bxr = (uint32_t)(brow & 7) << 4;
    #define ISSUE(s_) do { \
        int _t = tile0 + ((s_) >> 1), _kh = (s_) & 1; \
        const char* _src = (const char*)(g_phi + (size_t)(_t * PTILE + brow) * DIM + _kh * 128 + bhalf * 64); \
        uint32_t _dst = sb + (((s_) & 1) ? SOFF_B1 : SOFF_B0); \
        _Pragma("unroll") \
        for (int _g = 0; _g < 8; _g++) { \
            uint32_t _kg = (uint32_t)(bhalf * 8 + _g); \
            CP_ASYNC16(_dst + brb + ((_kg << 4) ^ bxr), _src + _g * 16); \
        } \
        CP_COMMIT(); \
    } while (0)

    ISSUE(0);

    float d[4][8][4];

    #pragma unroll 1
    for (int t = tile0; t < tileEnd; t++) {
        const int pBase = t * PTILE;
        #pragma unroll
        for (int mt = 0; mt < 4; mt++)
            #pragma unroll
            for (int n = 0; n < 8; n++)
                #pragma unroll
                for (int e = 0; e < 4; e++) d[mt][n][e] = 0.0f;

        #pragma unroll
        for (int c = 0; c < 2; c++) {
            const int s = (t - tile0) * 2 + c;
            if (s + 1 < NCHK) { ISSUE(s + 1); CP_WAIT1(); } else { CP_WAIT0(); }
            if (c == 0 && tid < 128)
                spAB[tid] = make_float2(g_pA[pBase + tid], g_pB[pBase + tid]);
            __syncthreads();
            const uint32_t bbuf = sb + (c ? SOFF_B1 : SOFF_B0);
            #pragma unroll
            for (int kk = 0; kk < 8; kk++) {
                const int ks = c * 8 + kk;
                uint32_t a[4][4];
                uint32_t aoffk = ((uint32_t)((ks * 2 + mh) << 4)) ^ xr;
                #pragma unroll
                for (int mt = 0; mt < 4; mt++)
                    ldsm_x4(a[mt][0], a[mt][1], a[mt][2], a[mt][3], aBase[mt] + aoffk);
                uint32_t boffk = ((uint32_t)((kk * 2 + mh) << 4)) ^ xr;
                #pragma unroll
                for (int n16 = 0; n16 < 4; n16++) {
                    uint32_t b0, b1, b2, b3;
                    ldsm_x4(b0, b1, b2, b3, bbuf + bBase[n16] + boffk);
                    #pragma unroll
                    for (int mt = 0; mt < 4; mt++) {
                        mma16816(d[mt][n16 * 2 + 0], a[mt], b0, b2);
                        mma16816(d[mt][n16 * 2 + 1], a[mt], b1, b3);
                    }
                }
            }
            __syncthreads();
        }

        // ---- in-register epilogue: weight + bucket top-3 ----
        #pragma unroll
        for (int n = 0; n < 8; n++) {
            int c0 = wp * 64 + n * 8 + (lane & 3) * 2;
            float4 w = *(const float4*)((const char*)spAB + (size_t)c0 * 8);
            int p0 = pBase + c0;
            bool ok0 = (p0 < MP), ok1 = (p0 + 1 < MP);
            #pragma unroll
            for (int mt = 0; mt < 4; mt++) {
                const int j0 = mt * 2, j1 = mt * 2 + 1;
                float s00 = d[mt][n][0] * fminf(eqr[j0] * w.x, ieqr[j0] * w.y);
                float s01 = d[mt][n][1] * fminf(eqr[j0] * w.z, ieqr[j0] * w.w);
                float s10 = d[mt][n][2] * fminf(eqr[j1] * w.x, ieqr[j1] * w.y);
                float s11 = d[mt][n][3] * fminf(eqr[j1] * w.z, ieqr[j1] * w.w);
                if (ok0) {
                    ins3(s00, p0, tv0[j0], ti0[j0], tv1[j0], ti1[j0], tv2[j0], ti2[j0]);
                    ins3(s10, p0, tv0[j1], ti0[j1], tv1[j1], ti1[j1], tv2[j1], ti2[j1]);
                }
                if (ok1) {
                    ins3(s01, p0 + 1, tv0[j0], ti0[j0], tv1[j0], ti1[j0], tv2[j0], ti2[j0]);
                    ins3(s11, p0 + 1, tv0[j1], ti0[j1], tv1[j1], ti1[j1], tv2[j1], ti2[j1]);
                }
            }
        }
        __syncthreads();   // protect spAB before next tile's write
    }

    // ---- final merge: 8 buckets x 3 per row -> top-12 per (q, chunk) ----
    float2* mb = (float2*)(smem + SOFF_B0);   // [256 rows][8 slots][3]
    const int slot = wp * 4 + (lane & 3);
    #pragma unroll
    for (int mt = 0; mt < 4; mt++)
        #pragma unroll
        for (int h = 0; h < 2; h++) {
            int r = wq * 64 + mt * 16 + g + h * 8;
            int j = mt * 2 + h;
            int base = (r * 8 + slot) * 3;
            mb[base + 0] = make_float2(tv0[j], __int_as_float(ti0[j]));
            mb[base + 1] = make_float2(tv1[j], __int_as_float(ti1[j]));
            mb[base + 2] = make_float2(tv2[j], __int_as_float(ti2[j]));
        }
    __syncthreads();
    {
        float bv[KC]; int bi[KC];
        #pragma unroll
        for (int u = 0; u < KC; u++) { bv[u] = -FLT_MAX; bi[u] = 0x7fffffff; }
        for (int c2 = 0; c2 < 24; c2++) {
            float2 e = mb[tid * 24 + c2];
            float s = e.x; int id = __float_as_int(e.y);
            if (better(s, id, bv[KC - 1], bi[KC - 1])) {
                int pos = KC - 1;
                while (pos > 0 && better(s, id, bv[pos - 1], bi[pos - 1])) {
                    bv[pos] = bv[pos - 1]; bi[pos] = bi[pos - 1]; pos--;
                }
                bv[pos] = s; bi[pos] = id;
            }
        }
        size_t base = ((size_t)(qBase + tid) * NCH + ch) * KC;
        #pragma unroll
        for (int u = 0; u < KC; u++) { g_cv[base + u] = bv[u]; g_ci[base + u] = bi[u]; }
    }
}

// ---------------- kernel 3: approx top-28 filter + exact fp32 rescore ----------------
__global__ __launch_bounds__(256)
void rescore_kernel(const float* __restrict__ pe) {
    __shared__ float qs[DIM];
    __shared__ float2 cand[NCH * KC];   // 444
    __shared__ int   sel[TOPC];
    __shared__ float scv[TOPC];
    const int q = blockIdx.x;
    const int tid = threadIdx.x, wid = tid >> 5, lane = tid & 31;
    qs[tid] = g_qn[q * DIM + tid];
    for (int i = tid; i < NCH * KC; i += 256) {
        cand[i] = make_float2(g_cv[(size_t)q * NCH * KC + i],
                              __int_as_float(g_ci[(size_t)q * NCH * KC + i]));
    }
    __syncthreads();
    if (tid == 0) {
        float bv[TOPC]; int bi[TOPC];
        #pragma unroll
        for (int u = 0; u < TOPC; u++) { bv[u] = -FLT_MAX; bi[u] = 0x7fffffff; }
        for (int c = 0; c < NCH * KC; c++) {
            float2 e = cand[c];
            float s = e.x; int id = __float_as_int(e.y);
            if (better(s, id, bv[TOPC - 1], bi[TOPC - 1])) {
                int pos = TOPC - 1;
                while (pos > 0 && better(s, id, bv[pos - 1], bi[pos - 1])) {
                    bv[pos] = bv[pos - 1]; bi[pos] = bi[pos - 1]; pos--;
                }
                bv[pos] = s; bi[pos] = id;
            }
        }
        #pragma unroll
        for (int u = 0; u < TOPC; u++) sel[u] = bi[u];
    }
    __syncthreads();
    const float eqv = g_eq[q], ieqv = g_ieq[q];
    for (int r = 0; r < 4; r++) {
        int c = wid + 8 * r;
        if (c >= TOPC) break;
        int idx = sel[c];
        float s = -FLT_MAX;
        if (idx < MP) {
            const float4* pp = (const float4*)(pe + (size_t)idx * DIM) + lane * 2;
            const float4* qq = (const float4*)qs + lane * 2;
            float4 v0 = pp[0], v1 = pp[1], q0 = qq[0], q1 = qq[1];
            float acc = v0.x*q0.x + v0.y*q0.y + v0.z*q0.z + v0.w*q0.w
                      + v1.x*q1.x + v1.y*q1.y + v1.z*q1.z + v1.w*q1.w;
            #pragma unroll
            for (int o = 16; o > 0; o >>= 1) acc += __shfl_xor_sync(0xffffffff, acc, o);
            s = acc * fminf(eqv * g_pA[idx], ieqv * g_pB[idx]);
        }
        if (lane == 0) scv[c] = s;
    }
    __syncthreads();
    if (tid == 0) {
        float bv[KTOP]; int bi[KTOP];
        #pragma unroll
        for (int u = 0; u < KTOP; u++) { bv[u] = -FLT_MAX; bi[u] = 0x7fffffff; }
        for (int c = 0; c < TOPC; c++) {
            float s = scv[c]; int id = sel[c];
            if (id < MP && better(s, id, bv[KTOP - 1], bi[KTOP - 1])) {
                int pos = KTOP - 1;
                while (pos > 0 && better(s, id, bv[pos - 1], bi[pos - 1])) {
                    bv[pos] = bv[pos - 1]; bi[pos] = bi[pos - 1]; pos--;
                }
                bv[pos] = s; bi[pos] = id;
            }
        }
        #pragma unroll
        for (int u = 0; u < KTOP; u++) g_topi[q * KTOP + u] = bi[u];
    }
}

// ---------------- kernel 4: GCN epilogue + anomaly score ----------------
__global__ __launch_bounds__(256)
void finalize_kernel(const float* __restrict__ qe,
                     const float* __restrict__ pool,
                     const float* __restrict__ W,
                     const float* __restrict__ bvec,
                     float* __restrict__ out) {
    int q = blockIdx.x;
    int d = threadIdx.x;
    __shared__ float vsh[DIM];
    __shared__ float red[3][8];

    const float cw0 = 1.70710678f;
    const float cw6 = 0.5f;

    float acc = 0.0f;
    #pragma unroll
    for (int k = 0; k < KTOP; k++) {
        int id = g_topi[q * KTOP + k];
        float c = (k == 0) ? cw0 : ((k == 6) ? cw6 : 1.0f);
        acc += c * pool[(size_t)id * DIM + d];
    }
    vsh[d] = acc;
    __syncthreads();

    float f = 0.0f;
    #pragma unroll 8
    for (int j = 0; j < DIM; j++) f += vsh[j] * W[j * DIM + d];
    f = f * (1.0f / 7.0f) + bvec[d];

    float qnv = g_qn[q * DIM + d];
    float qev = qe[q * DIM + d];
    float ff = f * f;
    float qf = qnv * f;
    float dd = (qev - f) * (qev - f);

    #pragma unroll
    for (int o = 16; o > 0; o >>= 1) {
        ff += __shfl_xor_sync(0xffffffff, ff, o);
        qf += __shfl_xor_sync(0xffffffff, qf, o);
        dd += __shfl_xor_sync(0xffffffff, dd, o);
    }
    int lane = d & 31, w = d >> 5;
    if (lane == 0) { red[0][w] = ff; red[1][w] = qf; red[2][w] = dd; }
    __syncthreads();
    if (d == 0) {
        float FF = 0, QF = 0, DD = 0;
        #pragma unroll
        for (int i = 0; i < 8; i++) { FF += red[0][i]; QF += red[1][i]; DD += red[2][i]; }
        float nf   = sqrtf(FF);
        float cosv = QF / fmaxf(nf, 1e-8f);
        out[q] = 0.6f * (1.0f - cosv) + 0.4f * sqrtf(DD);
    }
}

// ---------------- launcher ----------------
extern "C" void kernel_launch(void* const* d_in, const int* in_sizes, int n_in,
                              void* d_out, int out_size) {
    const float* qe  = (const float*)d_in[0];
    const float* qt  = (const float*)d_in[1];
    const float* pe  = (const float*)d_in[2];
    const float* pt  = (const float*)d_in[3];
    const float* lam = (const float*)d_in[4];
    const float* W   = (const float*)d_in[5];
    const float* b   = (const float*)d_in[6];
    float* out = (float*)d_out;

    static int configured = 0;
    if (!configured) {
        cudaFuncSetAttribute(main_topk_kernel,
                             cudaFuncAttributeMaxDynamicSharedMemorySize, SMEM_TOTAL);
        configured = 1;
    }

    prep_query_kernel<<<NQ / 8, 256>>>(qe, qt, lam);
    prep_pool_kernel<<<(MPPAD + 7) / 8, 256>>>(pe, pt, lam);
    dim3 grid(NQ / QTILE, NCH);
    main_topk_kernel<<<grid, 256, SMEM_TOTAL>>>();
    rescore_kernel<<<NQ, 256>>>(pe);
    finalize_kernel<<<NQ, 256>>>(qe, pe, W, b, out);
}

// round 6
// speedup vs baseline: 7.3897x; 1.4139x over previous
#include <cuda_runtime.h>
#include <cuda_bf16.h>
#include <math.h>
#include <float.h>
#include <stdint.h>

#define NQ    1024
#define MP    100000
#define DIM   256
#define KTOP  7
#define QTILE 128
#define PTILE 256
#define NT    391            // ceil(100000/256)
#define NCH   18             // chunks; grid = 8 x 18 = 144 CTAs (one wave)
#define KC    12             // candidates per (q, chunk)
#define TOPC  28             // global approx filter size before exact rescore
#define MPPAD (NT*PTILE)     // 100096

// ---------------- device scratch ----------------
__device__ float g_qn[NQ * DIM];
__device__ float g_eq[NQ];
__device__ float g_ieq[NQ];
__device__ float g_pA[MPPAD];   // pinv * exp(-l*pt)
__device__ float g_pB[MPPAD];   // pinv * exp(+l*pt)
__device__ __nv_bfloat16 g_qhi[NQ * DIM];
__device__ __nv_bfloat16 g_phi[(size_t)MPPAD * DIM];
__device__ float g_cv[(size_t)NQ * NCH * KC];
__device__ int   g_ci[(size_t)NQ * NCH * KC];
__device__ int   g_topi[NQ * KTOP];

__device__ __forceinline__ bool better(float s1, int i1, float s2, int i2) {
    return (s1 > s2) || (s1 == s2 && i1 < i2);
}

__device__ __forceinline__ uint32_t smem_to_u32(const void* p) {
    uint32_t a;
    asm("{ .reg .u64 t; cvta.to.shared.u64 t, %1; cvt.u32.u64 %0, t; }" : "=r"(a) : "l"(p));
    return a;
}
__device__ __forceinline__ void ldsm_x4(uint32_t& r0, uint32_t& r1, uint32_t& r2, uint32_t& r3,
                                        uint32_t addr) {
    asm volatile("ldmatrix.sync.aligned.m8n8.x4.shared.b16 {%0,%1,%2,%3}, [%4];"
        : "=r"(r0), "=r"(r1), "=r"(r2), "=r"(r3) : "r"(addr));
}
__device__ __forceinline__ void mma16816(float* d, const uint32_t* a, uint32_t b0, uint32_t b1) {
    asm volatile("mma.sync.aligned.m16n8k16.row.col.f32.bf16.bf16.f32 "
        "{%0,%1,%2,%3}, {%4,%5,%6,%7}, {%8,%9}, {%0,%1,%2,%3};"
        : "+f"(d[0]), "+f"(d[1]), "+f"(d[2]), "+f"(d[3])
        : "r"(a[0]), "r"(a[1]), "r"(a[2]), "r"(a[3]), "r"(b0), "r"(b1));
}
#define CP_ASYNC16(dst, src) asm volatile("cp.async.cg.shared.global [%0], [%1], 16;" :: "r"(dst), "l"(src))
#define CP_COMMIT() asm volatile("cp.async.commit_group;" ::: "memory")
#define CP_WAIT1()  asm volatile("cp.async.wait_group 1;" ::: "memory")
#define CP_WAIT0()  asm volatile("cp.async.wait_group 0;" ::: "memory")

// top-3 sorted insertion (hot path: one compare)
__device__ __forceinline__ void ins3(float s, int p,
                                     float& v0, int& i0, float& v1, int& i1,
                                     float& v2, int& i2) {
    if (better(s, p, v2, i2)) {
        if (better(s, p, v1, i1)) {
            v2 = v1; i2 = i1;
            if (better(s, p, v0, i0)) { v1 = v0; i1 = i0; v0 = s; i0 = p; }
            else { v1 = s; i1 = p; }
        } else { v2 = s; i2 = p; }
    }
}

// smem layout
#define SOFF_A    0                  // 65536: A 128x256 bf16, swizzled 512B rows
#define SOFF_B0   65536              // 65536: B chunk 256p x 128k bf16 (256B rows)
#define SOFF_B1   131072             // 65536
#define SOFF_PAB  196608             // 2048: float2[256] = (pA, pB)
#define SMEM_TOTAL 198656

// ---------------- kernel 0: query prep ----------------
__global__ void prep_query_kernel(const float* __restrict__ qe,
                                  const float* __restrict__ qt,
                                  const float* __restrict__ lam) {
    int row  = blockIdx.x * 8 + (threadIdx.x >> 5);
    int lane = threadIdx.x & 31;
    if (row >= NQ) return;
    const float4* src = (const float4*)(qe + row * DIM + lane * 8);
    float4 a = src[0], b = src[1];
    float ss = a.x*a.x + a.y*a.y + a.z*a.z + a.w*a.w
             + b.x*b.x + b.y*b.y + b.z*b.z + b.w*b.w;
    #pragma unroll
    for (int o = 16; o > 0; o >>= 1) ss += __shfl_xor_sync(0xffffffff, ss, o);
    float inv = 1.0f / fmaxf(sqrtf(ss), 1e-8f);
    float v[8] = {a.x*inv, a.y*inv, a.z*inv, a.w*inv, b.x*inv, b.y*inv, b.z*inv, b.w*inv};
    float4* dst = (float4*)(g_qn + row * DIM + lane * 8);
    dst[0] = make_float4(v[0], v[1], v[2], v[3]);
    dst[1] = make_float4(v[4], v[5], v[6], v[7]);
    __nv_bfloat16 hv[8];
    #pragma unroll
    for (int i = 0; i < 8; i++) hv[i] = __float2bfloat16(v[i]);
    *(uint4*)(g_qhi + row * DIM + lane * 8) = *(uint4*)hv;
    if (lane == 0) {
        float l = lam[0], t = qt[row];
        g_eq[row]  = expf(l * t);
        g_ieq[row] = expf(-l * t);
    }
}

// ---------------- kernel 1: pool prep (padded to MPPAD) ----------------
__global__ void prep_pool_kernel(const float* __restrict__ pe,
                                 const float* __restrict__ pt,
                                 const float* __restrict__ lam) {
    int row  = blockIdx.x * 8 + (threadIdx.x >> 5);
    int lane = threadIdx.x & 31;
    if (row >= MPPAD) return;
    if (row >= MP) {
        *(uint4*)(g_phi + (size_t)row * DIM + lane * 8) = make_uint4(0, 0, 0, 0);
        if (lane == 0) { g_pA[row] = 0.f; g_pB[row] = 0.f; }
        return;
    }
    const float4* src = (const float4*)(pe + (size_t)row * DIM + lane * 8);
    float4 a = src[0], b = src[1];
    float ss = a.x*a.x + a.y*a.y + a.z*a.z + a.w*a.w
             + b.x*b.x + b.y*b.y + b.z*b.z + b.w*b.w;
    #pragma unroll
    for (int o = 16; o > 0; o >>= 1) ss += __shfl_xor_sync(0xffffffff, ss, o);
    float v[8] = {a.x, a.y, a.z, a.w, b.x, b.y, b.z, b.w};
    __nv_bfloat16 hv[8];
    #pragma unroll
    for (int i = 0; i < 8; i++) hv[i] = __float2bfloat16(v[i]);
    *(uint4*)(g_phi + (size_t)row * DIM + lane * 8) = *(uint4*)hv;
    if (lane == 0) {
        float inv = 1.0f / fmaxf(sqrtf(ss), 1e-8f);
        float l = lam[0], t = pt[row];
        g_pA[row] = inv * expf(-l * t);
        g_pB[row] = inv * expf(l * t);
    }
}

// ---------------- kernel 2: HMMA GEMM (512 thr), in-register epilogue ----------------
__global__ __launch_bounds__(512, 1)
void main_topk_kernel() {
    extern __shared__ char smem[];
    const uint32_t sb = smem_to_u32(smem);
    float2* spAB = (float2*)(smem + SOFF_PAB);

    const int tid = threadIdx.x;
    const int wid = tid >> 5, lane = tid & 31;
    const int wq = wid >> 2, wp = wid & 3;     // 4q x 4p warps, warp tile 32q x 64p
    const int qBase = blockIdx.x * QTILE;
    const int ch = blockIdx.y;
    const int tile0   = (ch * NT) / NCH;
    const int tileEnd = ((ch + 1) * NT) / NCH;
    const int NCHK = (tileEnd - tile0) * 2;    // 128k chunks total

    // ---- load A once (128 rows x 512B, swizzled) ----
    {
        int row = tid >> 2, part = tid & 3;
        const uint4* asrc = (const uint4*)(g_qhi + (size_t)(qBase + row) * DIM) + part * 8;
        uint32_t arb = (uint32_t)row * 512;
        uint32_t xr0 = (uint32_t)(row & 7) << 4;
        #pragma unroll
        for (int g2 = 0; g2 < 8; g2++) {
            uint32_t kg = (uint32_t)(part * 8 + g2);
            *(uint4*)(smem + SOFF_A + arb + ((kg << 4) ^ xr0)) = asrc[g2];
        }
    }

    // per-thread row weights (4 rows, fixed all kernel)
    const int g = lane >> 2;
    float eqr[4], ieqr[4];
    #pragma unroll
    for (int mt = 0; mt < 2; mt++)
        #pragma unroll
        for (int h = 0; h < 2; h++) {
            int r = qBase + wq * 32 + mt * 16 + g + h * 8;
            eqr[mt * 2 + h]  = g_eq[r];
            ieqr[mt * 2 + h] = g_ieq[r];
        }

    // fragment addressing
    const int mh = (lane >> 4) & 1;
    const int mlow = (lane >> 3) & 1;
    const int lr = lane & 7;
    const uint32_t xr = (uint32_t)lr << 4;
    uint32_t aBase[2], bBase[4];
    #pragma unroll
    for (int mt = 0; mt < 2; mt++)
        aBase[mt] = sb + SOFF_A + (uint32_t)(wq * 32 + mt * 16 + mlow * 8 + lr) * 512;
    #pragma unroll
    for (int n16 = 0; n16 < 4; n16++)
        bBase[n16] = (uint32_t)(wp * 64 + n16 * 16 + mlow * 8 + lr) * 256;

    // bucket top-3 per (thread, row)
    float tv0[4], tv1[4], tv2[4]; int ti0[4], ti1[4], ti2[4];
    #pragma unroll
    for (int j = 0; j < 4; j++) {
        tv0[j] = tv1[j] = tv2[j] = -FLT_MAX;
        ti0[j] = ti1[j] = ti2[j] = 0x7fffffff;
    }

    // cp.async for chunk s (256p x 128k = 64KB): 2 threads/row, 8 x 16B each
    const int brow = tid >> 1, bhalf = tid & 1;
    const uint32_t brb = (uint32_t)brow * 256;
    const uint32_t bxr = (uint32_t)(brow & 7) << 4;
    #define ISSUE(s_) do { \
        int _t = tile0 + ((s_) >> 1), _kh = (s_) & 1; \
        const char* _src = (const char*)(g_phi + (size_t)(_t * PTILE + brow) * DIM + _kh * 128 + bhalf * 64); \
        uint32_t _dst = sb + (((s_) & 1) ? SOFF_B1 : SOFF_B0); \
        _Pragma("unroll") \
        for (int _g = 0; _g < 8; _g++) { \
            uint32_t _kg = (uint32_t)(bhalf * 8 + _g); \
            CP_ASYNC16(_dst + brb + ((_kg << 4) ^ bxr), _src + _g * 16); \
        } \
        CP_COMMIT(); \
    } while (0)

    ISSUE(0);

    float d[2][8][4];

    #pragma unroll 1
    for (int t = tile0; t < tileEnd; t++) {
        const int pBase = t * PTILE;
        #pragma unroll
        for (int mt = 0; mt < 2; mt++)
            #pragma unroll
            for (int n = 0; n < 8; n++)
                #pragma unroll
                for (int e = 0; e < 4; e++) d[mt][n][e] = 0.0f;

        #pragma unroll
        for (int c = 0; c < 2; c++) {
            const int s = (t - tile0) * 2 + c;
            if (s + 1 < NCHK) { ISSUE(s + 1); CP_WAIT1(); } else { CP_WAIT0(); }
            if (c == 0 && tid < 256)
                spAB[tid] = make_float2(g_pA[pBase + tid], g_pB[pBase + tid]);
            __syncthreads();
            const uint32_t bbuf = sb + (c ? SOFF_B1 : SOFF_B0);
            #pragma unroll
            for (int kk = 0; kk < 8; kk++) {
                const int ks = c * 8 + kk;
                uint32_t a[2][4];
                uint32_t aoffk = ((uint32_t)((ks * 2 + mh) << 4)) ^ xr;
                ldsm_x4(a[0][0], a[0][1], a[0][2], a[0][3], aBase[0] + aoffk);
                ldsm_x4(a[1][0], a[1][1], a[1][2], a[1][3], aBase[1] + aoffk);
                uint32_t boffk = ((uint32_t)((kk * 2 + mh) << 4)) ^ xr;
                #pragma unroll
                for (int n16 = 0; n16 < 4; n16++) {
                    uint32_t b0, b1, b2, b3;
                    ldsm_x4(b0, b1, b2, b3, bbuf + bBase[n16] + boffk);
                    mma16816(d[0][n16 * 2 + 0], a[0], b0, b2);
                    mma16816(d[0][n16 * 2 + 1], a[0], b1, b3);
                    mma16816(d[1][n16 * 2 + 0], a[1], b0, b2);
                    mma16816(d[1][n16 * 2 + 1], a[1], b1, b3);
                }
            }
            __syncthreads();
        }

        // ---- in-register epilogue: weight + bucket top-3 ----
        #pragma unroll
        for (int n = 0; n < 8; n++) {
            int c0 = wp * 64 + n * 8 + (lane & 3) * 2;
            float4 w = *(const float4*)((const char*)spAB + (size_t)c0 * 8);
            int p0 = pBase + c0;
            bool ok0 = (p0 < MP), ok1 = (p0 + 1 < MP);
            #pragma unroll
            for (int mt = 0; mt < 2; mt++) {
                const int j0 = mt * 2, j1 = mt * 2 + 1;
                float s00 = d[mt][n][0] * fminf(eqr[j0] * w.x, ieqr[j0] * w.y);
                float s01 = d[mt][n][1] * fminf(eqr[j0] * w.z, ieqr[j0] * w.w);
                float s10 = d[mt][n][2] * fminf(eqr[j1] * w.x, ieqr[j1] * w.y);
                float s11 = d[mt][n][3] * fminf(eqr[j1] * w.z, ieqr[j1] * w.w);
                if (ok0) {
                    ins3(s00, p0, tv0[j0], ti0[j0], tv1[j0], ti1[j0], tv2[j0], ti2[j0]);
                    ins3(s10, p0, tv0[j1], ti0[j1], tv1[j1], ti1[j1], tv2[j1], ti2[j1]);
                }
                if (ok1) {
                    ins3(s01, p0 + 1, tv0[j0], ti0[j0], tv1[j0], ti1[j0], tv2[j0], ti2[j0]);
                    ins3(s11, p0 + 1, tv0[j1], ti0[j1], tv1[j1], ti1[j1], tv2[j1], ti2[j1]);
                }
            }
        }
        __syncthreads();   // protect spAB before next tile's write
    }

    // ---- final merge: 16 buckets x 3 per row -> top-12 per (q, chunk) ----
    float2* mb = (float2*)(smem + SOFF_B0);   // [128 rows][16 slots][3] = 48KB
    const int slot = wp * 4 + (lane & 3);
    #pragma unroll
    for (int mt = 0; mt < 2; mt++)
        #pragma unroll
        for (int h = 0; h < 2; h++) {
            int r = wq * 32 + mt * 16 + g + h * 8;
            int j = mt * 2 + h;
            int base = (r * 16 + slot) * 3;
            mb[base + 0] = make_float2(tv0[j], __int_as_float(ti0[j]));
            mb[base + 1] = make_float2(tv1[j], __int_as_float(ti1[j]));
            mb[base + 2] = make_float2(tv2[j], __int_as_float(ti2[j]));
        }
    __syncthreads();
    if (tid < 128) {
        float bv[KC]; int bi[KC];
        #pragma unroll
        for (int u = 0; u < KC; u++) { bv[u] = -FLT_MAX; bi[u] = 0x7fffffff; }
        for (int c2 = 0; c2 < 48; c2++) {
            float2 e = mb[tid * 48 + c2];
            float s = e.x; int id = __float_as_int(e.y);
            if (better(s, id, bv[KC - 1], bi[KC - 1])) {
                int pos = KC - 1;
                while (pos > 0 && better(s, id, bv[pos - 1], bi[pos - 1])) {
                    bv[pos] = bv[pos - 1]; bi[pos] = bi[pos - 1]; pos--;
                }
                bv[pos] = s; bi[pos] = id;
            }
        }
        size_t base = ((size_t)(qBase + tid) * NCH + ch) * KC;
        #pragma unroll
        for (int u = 0; u < KC; u++) { g_cv[base + u] = bv[u]; g_ci[base + u] = bi[u]; }
    }
}

// ---------------- kernel 3: parallel top-28 filter + exact fp32 rescore ----------------
#define TOT (NCH * KC)    // 216
#define PERLANE ((TOT + 31) / 32)   // 7
__global__ __launch_bounds__(256)
void rescore_kernel(const float* __restrict__ pe) {
    __shared__ float qs[DIM];
    __shared__ int   sel[32];
    __shared__ float scv[32];
    const int q = blockIdx.x;
    const int tid = threadIdx.x, wid = tid >> 5, lane = tid & 31;
    qs[tid] = g_qn[q * DIM + tid];
    __syncthreads();

    // warp 0: iterative argmax extraction of top-28 (value, poolidx) with slot clearing
    if (wid == 0) {
        float cv[PERLANE]; int cix[PERLANE];
        #pragma unroll
        for (int j = 0; j < PERLANE; j++) {
            int c = lane * PERLANE + j;
            if (c < TOT) {
                cv[j]  = g_cv[(size_t)q * TOT + c];
                cix[j] = g_ci[(size_t)q * TOT + c];
            } else { cv[j] = -FLT_MAX; cix[j] = 0x7fffffff; }
        }
        for (int u = 0; u < TOPC; u++) {
            // local argmax
            float lv = cv[0]; int lix = cix[0]; int lsl = 0;
            #pragma unroll
            for (int j = 1; j < PERLANE; j++)
                if (better(cv[j], cix[j], lv, lix)) { lv = cv[j]; lix = cix[j]; lsl = j; }
            // warp argmax carrying (v, idx, lane*8+slot)
            int lpos = lane * PERLANE + lsl;
            #pragma unroll
            for (int o = 16; o > 0; o >>= 1) {
                float ov = __shfl_xor_sync(0xffffffff, lv, o);
                int   oi = __shfl_xor_sync(0xffffffff, lix, o);
                int   op = __shfl_xor_sync(0xffffffff, lpos, o);
                if (better(ov, oi, lv, lix)) { lv = ov; lix = oi; lpos = op; }
            }
            if (lane == 0) { sel[u] = lix; }
            // clear the winning slot
            if ((lpos / PERLANE) == lane) cv[lpos % PERLANE] = -FLT_MAX, cix[lpos % PERLANE] = 0x7fffffff;
        }
    }
    __syncthreads();

    const float eqv = g_eq[q], ieqv = g_ieq[q];
    for (int r = 0; r < 4; r++) {
        int c = wid + 8 * r;
        if (c >= TOPC) break;
        int idx = sel[c];
        float s = -FLT_MAX;
        if (idx < MP) {
            const float4* pp = (const float4*)(pe + (size_t)idx * DIM) + lane * 2;
            const float4* qq = (const float4*)qs + lane * 2;
            float4 v0 = pp[0], v1 = pp[1], q0 = qq[0], q1 = qq[1];
            float acc = v0.x*q0.x + v0.y*q0.y + v0.z*q0.z + v0.w*q0.w
                      + v1.x*q1.x + v1.y*q1.y + v1.z*q1.z + v1.w*q1.w;
            #pragma unroll
            for (int o = 16; o > 0; o >>= 1) acc += __shfl_xor_sync(0xffffffff, acc, o);
            s = acc * fminf(eqv * g_pA[idx], ieqv * g_pB[idx]);
        }
        if (lane == 0) scv[c] = s;
    }
    __syncthreads();
    if (tid == 0) {
        float bv[KTOP]; int bi[KTOP];
        #pragma unroll
        for (int u = 0; u < KTOP; u++) { bv[u] = -FLT_MAX; bi[u] = 0x7fffffff; }
        for (int c = 0; c < TOPC; c++) {
            float s = scv[c]; int id = sel[c];
            if (id < MP && better(s, id, bv[KTOP - 1], bi[KTOP - 1])) {
                int pos = KTOP - 1;
                while (pos > 0 && better(s, id, bv[pos - 1], bi[pos - 1])) {
                    bv[pos] = bv[pos - 1]; bi[pos] = bi[pos - 1]; pos--;
                }
                bv[pos] = s; bi[pos] = id;
            }
        }
        #pragma unroll
        for (int u = 0; u < KTOP; u++) g_topi[q * KTOP + u] = bi[u];
    }
}

// ---------------- kernel 4: GCN epilogue + anomaly score ----------------
__global__ __launch_bounds__(256)
void finalize_kernel(const float* __restrict__ qe,
                     const float* __restrict__ pool,
                     const float* __restrict__ W,
                     const float* __restrict__ bvec,
                     float* __restrict__ out) {
    int q = blockIdx.x;
    int d = threadIdx.x;
    __shared__ float vsh[DIM];
    __shared__ float red[3][8];

    const float cw0 = 1.70710678f;
    const float cw6 = 0.5f;

    float acc = 0.0f;
    #pragma unroll
    for (int k = 0; k < KTOP; k++) {
        int id = g_topi[q * KTOP + k];
        float c = (k == 0) ? cw0 : ((k == 6) ? cw6 : 1.0f);
        acc += c * pool[(size_t)id * DIM + d];
    }
    vsh[d] = acc;
    __syncthreads();

    float f = 0.0f;
    #pragma unroll 8
    for (int j = 0; j < DIM; j++) f += vsh[j] * W[j * DIM + d];
    f = f * (1.0f / 7.0f) + bvec[d];

    float qnv = g_qn[q * DIM + d];
    float qev = qe[q * DIM + d];
    float ff = f * f;
    float qf = qnv * f;
    float dd = (qev - f) * (qev - f);

    #pragma unroll
    for (int o = 16; o > 0; o >>= 1) {
        ff += __shfl_xor_sync(0xffffffff, ff, o);
        qf += __shfl_xor_sync(0xffffffff, qf, o);
        dd += __shfl_xor_sync(0xffffffff, dd, o);
    }
    int lane = d & 31, w = d >> 5;
    if (lane == 0) { red[0][w] = ff; red[1][w] = qf; red[2][w] = dd; }
    __syncthreads();
    if (d == 0) {
        float FF = 0, QF = 0, DD = 0;
        #pragma unroll
        for (int i = 0; i < 8; i++) { FF += red[0][i]; QF += red[1][i]; DD += red[2][i]; }
        float nf   = sqrtf(FF);
        float cosv = QF / fmaxf(nf, 1e-8f);
        out[q] = 0.6f * (1.0f - cosv) + 0.4f * sqrtf(DD);
    }
}

// ---------------- launcher ----------------
extern "C" void kernel_launch(void* const* d_in, const int* in_sizes, int n_in,
                              void* d_out, int out_size) {
    const float* qe  = (const float*)d_in[0];
    const float* qt  = (const float*)d_in[1];
    const float* pe  = (const float*)d_in[2];
    const float* pt  = (const float*)d_in[3];
    const float* lam = (const float*)d_in[4];
    const float* W   = (const float*)d_in[5];
    const float* b   = (const float*)d_in[6];
    float* out = (float*)d_out;

    static int configured = 0;
    if (!configured) {
        cudaFuncSetAttribute(main_topk_kernel,
                             cudaFuncAttributeMaxDynamicSharedMemorySize, SMEM_TOTAL);
        configured = 1;
    }

    prep_query_kernel<<<NQ / 8, 256>>>(qe, qt, lam);
    prep_pool_kernel<<<(MPPAD + 7) / 8, 256>>>(pe, pt, lam);
    dim3 grid(NQ / QTILE, NCH);
    main_topk_kernel<<<grid, 512, SMEM_TOTAL>>>();
    rescore_kernel<<<NQ, 256>>>(pe);
    finalize_kernel<<<NQ, 256>>>(qe, pe, W, b, out);
}